// round 10
// baseline (speedup 1.0000x reference)
#include <cuda_runtime.h>
#include <cuda_bf16.h>

// ---------------- problem constants ----------------
constexpr int kNH = 6;
constexpr int kD  = 768;
constexpr int kHD = 128;
constexpr int kB  = 2;
constexpr int kT  = 2048;
constexpr int kBT = kB * kT;          // 4096
constexpr float kEPS = 1e-6f;

constexpr int PITCH = 132;            // smem pitch (float4-aligned, conflict-reducing)
constexpr int GP    = 132;            // gemm smem pitch

typedef unsigned long long ull;

// ---------------- device scratch (no allocation allowed) ----------------
__device__ float d_Z   [kNH * kBT * kHD];   // x @ phi   (inner)
__device__ float d_ZPSI[kNH * kBT * kHD];   // x @ psi   (query)
__device__ float d_P   [kNH * kBT * kHD];   // g @ (x*s)
__device__ float d_Q   [kNH * kBT * kHD];   // scan output per head
__device__ float d_SX  [kNH * kBT];         // sum_d x*s
__device__ float d_G   [kNH * kHD * kHD];   // g g^T
__device__ float d_G2  [kNH * kHD * kHD];   // g diag(s^2) g^T
__device__ float d_g1  [kNH * kHD];
__device__ float d_v2  [kNH * kHD];
__device__ float d_vbs [kNH * kHD];
__device__ float d_S2  [kNH];
__device__ float d_SBS [kNH];
__device__ int   d_flag[1];

// ---------------- f32x2 packed helpers ----------------
__device__ __forceinline__ ull fma2(ull a, ull b, ull c) {
    ull d;
    asm("fma.rn.f32x2 %0, %1, %2, %3;" : "=l"(d) : "l"(a), "l"(b), "l"(c));
    return d;
}
__device__ __forceinline__ ull pack2(float lo, float hi) {
    ull r;
    asm("mov.b64 %0, {%1, %2};" : "=l"(r) : "f"(lo), "f"(hi));
    return r;
}
__device__ __forceinline__ float hsum2(ull v) {
    float lo, hi;
    asm("mov.b64 {%0, %1}, %2;" : "=f"(lo), "=f"(hi) : "l"(v));
    return lo + hi;
}
__device__ __forceinline__ float warpsum(float v) {
    #pragma unroll
    for (int o = 16; o > 0; o >>= 1) v += __shfl_xor_sync(0xFFFFFFFFu, v, o);
    return v;
}

// ---------------- fast-path detection: ln_scale==1, ln_bias==0 ----------------
__global__ void flag_kernel(const float* __restrict__ s, const float* __restrict__ b) {
    __shared__ int sok;
    if (threadIdx.x == 0) sok = 1;
    __syncthreads();
    int ok = 1;
    for (int i = threadIdx.x; i < kNH * kD; i += 256)
        ok &= (s[i] == 1.0f) && (b[i] == 0.0f);
    if (!ok) atomicAnd(&sok, 0);
    __syncthreads();
    if (threadIdx.x == 0) d_flag[0] = sok;
}

// ---------------- per-head constants G = g g^T (mode 0), G2 = g diag(s^2) g^T (mode 1) ----------------
__global__ void __launch_bounds__(256) consts_kernel(const float* __restrict__ g,
                                                     const float* __restrict__ s) {
    const int k = blockIdx.x;
    const int mode = blockIdx.y;     // 0 -> G, 1 -> G2
    __shared__ float gsh[128 * 33];
    __shared__ float wsh[32];
    const int tid = threadIdx.x;
    const int tx = tid & 15, ty = tid >> 4;
    float acc[8][8];
    #pragma unroll
    for (int r = 0; r < 8; r++)
        #pragma unroll
        for (int c = 0; c < 8; c++) acc[r][c] = 0.f;

    for (int d0 = 0; d0 < kD; d0 += 32) {
        for (int f = tid; f < 128 * 32; f += 256) {
            int i = f >> 5, dd = f & 31;
            gsh[i * 33 + dd] = g[(k * kHD + i) * kD + d0 + dd];
        }
        if (tid < 32) {
            float sv = s[k * kD + d0 + tid];
            wsh[tid] = mode ? sv * sv : 1.0f;
        }
        __syncthreads();
        #pragma unroll 4
        for (int dd = 0; dd < 32; dd++) {
            float wv = wsh[dd];
            float a[8], bb[8];
            #pragma unroll
            for (int r = 0; r < 8; r++) a[r] = gsh[(ty * 8 + r) * 33 + dd] * wv;
            #pragma unroll
            for (int c = 0; c < 8; c++) bb[c] = gsh[(tx * 8 + c) * 33 + dd];
            #pragma unroll
            for (int r = 0; r < 8; r++)
                #pragma unroll
                for (int c = 0; c < 8; c++) acc[r][c] = fmaf(a[r], bb[c], acc[r][c]);
        }
        __syncthreads();
    }
    float* dst = (mode ? d_G2 : d_G) + k * kHD * kHD;
    #pragma unroll
    for (int r = 0; r < 8; r++)
        #pragma unroll
        for (int c = 0; c < 8; c++)
            dst[(ty * 8 + r) * kHD + tx * 8 + c] = acc[r][c];
}

// ---------------- row stats: g1, v2, vbs, S2, SBS ----------------
__global__ void rowstats_kernel(const float* __restrict__ g,
                                const float* __restrict__ s,
                                const float* __restrict__ b) {
    const int k = blockIdx.x;
    const int tid = threadIdx.x;   // 256
    if (tid < 128) {
        float a1 = 0.f, a2 = 0.f, a3 = 0.f;
        const float* grow = g + (k * kHD + tid) * kD;
        const float* srow = s + k * kD;
        const float* brow = b + k * kD;
        for (int d = 0; d < kD; d++) {
            float gv = grow[d], sv = srow[d], bv = brow[d];
            a1 += gv;
            a2 = fmaf(gv, sv * sv, a2);
            a3 = fmaf(gv, bv * sv, a3);
        }
        d_g1[k * kHD + tid]  = a1;
        d_v2[k * kHD + tid]  = a2;
        d_vbs[k * kHD + tid] = a3;
    }
    float s2p = 0.f, sbp = 0.f;
    for (int d = tid; d < kD; d += 256) {
        float sv = s[k * kD + d], bv = b[k * kD + d];
        s2p = fmaf(sv, sv, s2p);
        sbp = fmaf(bv, sv, sbp);
    }
    __shared__ float red[512];
    red[tid] = s2p; red[256 + tid] = sbp;
    __syncthreads();
    for (int o = 128; o > 0; o >>= 1) {
        if (tid < o) { red[tid] += red[tid + o]; red[256 + tid] += red[256 + tid + o]; }
        __syncthreads();
    }
    if (tid == 0) { d_S2[k] = red[0]; d_SBS[k] = red[256]; }
}

// ---------------- SX[k][bt] = sum_d X[bt][d] * s[k][d] ----------------
__global__ void sx_kernel(const float* __restrict__ X, const float* __restrict__ s) {
    const int bt = blockIdx.x;
    const int w = threadIdx.x >> 5;      // 0..5 (192 threads)
    const int lane = threadIdx.x & 31;
    float acc = 0.f;
    for (int d0 = lane * 4; d0 < kD; d0 += 128) {
        float4 xv = *(const float4*)&X[bt * kD + d0];
        float4 sv = *(const float4*)&s[w * kD + d0];
        acc = fmaf(xv.x, sv.x, acc);
        acc = fmaf(xv.y, sv.y, acc);
        acc = fmaf(xv.z, sv.z, acc);
        acc = fmaf(xv.w, sv.w, acc);
    }
    acc = warpsum(acc);
    if (lane == 0) d_SX[w * kBT + bt] = acc;
}

// ---------------- projection GEMMs: Z = X@phi, ZPSI = X@psi, P = X @ (g*s)^T ----------------
__global__ void __launch_bounds__(256) gemm_proj_kernel(const float* __restrict__ X,
                                                        const float* __restrict__ phi,
                                                        const float* __restrict__ psi,
                                                        const float* __restrict__ g,
                                                        const float* __restrict__ s) {
    const int which = blockIdx.z % 3;
    const int head  = blockIdx.z / 3;
    const int m0 = blockIdx.y * 128;
    __shared__ float As[16 * GP];
    __shared__ float Bs[16 * GP];
    const int tid = threadIdx.x;
    const int tx = tid & 15, ty = tid >> 4;
    ull acc2[8][4];
    #pragma unroll
    for (int r = 0; r < 8; r++)
        #pragma unroll
        for (int c = 0; c < 4; c++) acc2[r][c] = 0ULL;

    const float* Bsrc = (which == 0) ? phi : psi;

    for (int k0 = 0; k0 < kD; k0 += 16) {
        {
            int m = tid >> 2, kq = tid & 3;
            #pragma unroll
            for (int h2 = 0; h2 < 2; h2++) {
                int mm = m + h2 * 64;
                float4 v = *(const float4*)&X[(size_t)(m0 + mm) * kD + k0 + kq * 4];
                As[(kq * 4 + 0) * GP + mm] = v.x;
                As[(kq * 4 + 1) * GP + mm] = v.y;
                As[(kq * 4 + 2) * GP + mm] = v.z;
                As[(kq * 4 + 3) * GP + mm] = v.w;
            }
        }
        if (which < 2) {
            int f = tid;
            #pragma unroll
            for (int it = 0; it < 2; it++, f += 256) {
                int kk = f >> 5, n4 = f & 31;
                float4 v = *(const float4*)&Bsrc[(size_t)(head * kD + k0 + kk) * kHD + n4 * 4];
                *(float4*)&Bs[kk * GP + n4 * 4] = v;
            }
        } else {
            int f = tid;
            #pragma unroll
            for (int it = 0; it < 2; it++, f += 256) {
                int jj = f >> 2, kq = f & 3;
                float4 gv = *(const float4*)&g[(size_t)(head * kHD + jj) * kD + k0 + kq * 4];
                float4 sv = *(const float4*)&s[head * kD + k0 + kq * 4];
                Bs[(kq * 4 + 0) * GP + jj] = gv.x * sv.x;
                Bs[(kq * 4 + 1) * GP + jj] = gv.y * sv.y;
                Bs[(kq * 4 + 2) * GP + jj] = gv.z * sv.z;
                Bs[(kq * 4 + 3) * GP + jj] = gv.w * sv.w;
            }
        }
        __syncthreads();
        #pragma unroll
        for (int kk = 0; kk < 16; kk++) {
            float a[8];
            *(float4*)&a[0]  = *(const float4*)&As[kk * GP + ty * 8];
            *(float4*)&a[4]  = *(const float4*)&As[kk * GP + ty * 8 + 4];
            ulonglong2 b0 = *(const ulonglong2*)&Bs[kk * GP + tx * 8];
            ulonglong2 b1 = *(const ulonglong2*)&Bs[kk * GP + tx * 8 + 4];
            #pragma unroll
            for (int r = 0; r < 8; r++) {
                ull a2 = pack2(a[r], a[r]);
                acc2[r][0] = fma2(a2, b0.x, acc2[r][0]);
                acc2[r][1] = fma2(a2, b0.y, acc2[r][1]);
                acc2[r][2] = fma2(a2, b1.x, acc2[r][2]);
                acc2[r][3] = fma2(a2, b1.y, acc2[r][3]);
            }
        }
        __syncthreads();
    }
    float* Cdst = ((which == 0) ? d_Z : (which == 1) ? d_ZPSI : d_P) + (size_t)head * kBT * kHD;
    #pragma unroll
    for (int r = 0; r < 8; r++) {
        int m = m0 + ty * 8 + r;
        *(ulonglong2*)&Cdst[(size_t)m * kHD + tx * 8]     = make_ulonglong2(acc2[r][0], acc2[r][1]);
        *(ulonglong2*)&Cdst[(size_t)m * kHD + tx * 8 + 4] = make_ulonglong2(acc2[r][2], acc2[r][3]);
    }
}

// ---------------- output GEMM: out[bt][d] = sum_k sum_j Q[k][bt][j] * h[k][j][d] ----------------
__global__ void __launch_bounds__(256) gemm_out_kernel(const float* __restrict__ h,
                                                       float* __restrict__ out) {
    const int n0 = blockIdx.x * 128;   // over D = 768
    const int m0 = blockIdx.y * 128;   // over BT = 4096
    __shared__ float As[16 * GP];
    __shared__ float Bs[16 * GP];
    const int tid = threadIdx.x;
    const int tx = tid & 15, ty = tid >> 4;
    ull acc2[8][4];
    #pragma unroll
    for (int r = 0; r < 8; r++)
        #pragma unroll
        for (int c = 0; c < 4; c++) acc2[r][c] = 0ULL;

    for (int k0 = 0; k0 < kNH * kHD; k0 += 16) {
        const int head = k0 >> 7;
        const int j0 = k0 & 127;
        const float* Aq = d_Q + (size_t)head * kBT * kHD;
        {
            int m = tid >> 2, kq = tid & 3;
            #pragma unroll
            for (int h2 = 0; h2 < 2; h2++) {
                int mm = m + h2 * 64;
                float4 v = *(const float4*)&Aq[(size_t)(m0 + mm) * kHD + j0 + kq * 4];
                As[(kq * 4 + 0) * GP + mm] = v.x;
                As[(kq * 4 + 1) * GP + mm] = v.y;
                As[(kq * 4 + 2) * GP + mm] = v.z;
                As[(kq * 4 + 3) * GP + mm] = v.w;
            }
        }
        {
            int f = tid;
            #pragma unroll
            for (int it = 0; it < 2; it++, f += 256) {
                int kk = f >> 5, n4 = f & 31;
                float4 v = *(const float4*)&h[(size_t)(k0 + kk) * kD + n0 + n4 * 4];
                *(float4*)&Bs[kk * GP + n4 * 4] = v;
            }
        }
        __syncthreads();
        #pragma unroll
        for (int kk = 0; kk < 16; kk++) {
            float a[8];
            *(float4*)&a[0]  = *(const float4*)&As[kk * GP + ty * 8];
            *(float4*)&a[4]  = *(const float4*)&As[kk * GP + ty * 8 + 4];
            ulonglong2 b0 = *(const ulonglong2*)&Bs[kk * GP + tx * 8];
            ulonglong2 b1 = *(const ulonglong2*)&Bs[kk * GP + tx * 8 + 4];
            #pragma unroll
            for (int r = 0; r < 8; r++) {
                ull a2 = pack2(a[r], a[r]);
                acc2[r][0] = fma2(a2, b0.x, acc2[r][0]);
                acc2[r][1] = fma2(a2, b0.y, acc2[r][1]);
                acc2[r][2] = fma2(a2, b1.x, acc2[r][2]);
                acc2[r][3] = fma2(a2, b1.y, acc2[r][3]);
            }
        }
        __syncthreads();
    }
    #pragma unroll
    for (int r = 0; r < 8; r++) {
        int m = m0 + ty * 8 + r;
        *(ulonglong2*)&out[(size_t)m * kD + n0 + tx * 8]     = make_ulonglong2(acc2[r][0], acc2[r][1]);
        *(ulonglong2*)&out[(size_t)m * kD + n0 + tx * 8 + 4] = make_ulonglong2(acc2[r][2], acc2[r][3]);
    }
}

// ---------------- the sequential scan: one CTA per (head, batch) ----------------
// Thread map: j = tid>>1 (column), half = tid&1 (row half). W and G rows for
// (column j / row j) live in registers as 32 packed f32x2 each.
constexpr int SCAN_SMEM_FLOATS =
    128 * PITCH      // G2sh (generic path only)
    + 3 * 128        // zsh (triple buffer)
    + 2 * 128        // zpsh
    + 2 * 128        // Psh
    + 8 * 128        // ysh, ppsh, Gysh, G2ysh, dysh, g1sh, v2sh, vbssh
    + 24 + 8 + 8 + 4;
constexpr int SCAN_SMEM_BYTES = SCAN_SMEM_FLOATS * 4;

__global__ void __launch_bounds__(256, 1) scan_kernel(const float* __restrict__ W0,
                                                      const float* __restrict__ Gsrc) {
    extern __shared__ float sm[];
    float* G2sh  = sm;
    float* zsh   = G2sh + 128 * PITCH;   // 3 buffers of 128
    float* zpsh  = zsh + 384;            // 2 buffers
    float* Psh   = zpsh + 256;           // 2 buffers
    float* ysh   = Psh + 256;
    float* ppsh  = ysh + 128;
    float* Gysh  = ppsh + 128;
    float* G2ysh = Gysh + 128;
    float* dysh  = G2ysh + 128;
    float* g1sh  = dysh + 128;
    float* v2sh  = g1sh + 128;
    float* vbssh = v2sh + 128;
    float* dparts = vbssh + 128;   // 5 dots x 4 warp partials (padded 24)
    float* wsumA  = dparts + 24;   // su2 partials (8 warps)
    float* wsumB  = wsumA + 8;     // q2 partials
    float* sxs    = wsumB + 8;     // SX double buffer

    const int k = blockIdx.x;
    const int b = blockIdx.y;
    const int tid = threadIdx.x;
    const int j = tid >> 1;
    const int half = tid & 1;
    const bool fast = (d_flag[0] != 0);

    // ---- init smem ----
    if (!fast) {
        for (int idx = tid; idx < kHD * kHD; idx += 256) {
            int i = idx >> 7, jj = idx & 127;
            G2sh[i * PITCH + jj] = d_G2[k * kHD * kHD + idx];
        }
    }
    const int seqbase = (k * kBT + b * kT) * kHD;
    const int tb = k * kBT + b * kT;
    if (tid < 128) {
        g1sh[tid]  = d_g1[k * kHD + tid];
        v2sh[tid]  = d_v2[k * kHD + tid];
        vbssh[tid] = d_vbs[k * kHD + tid];
        dysh[tid]  = 0.f;
        zsh[2 * 128 + tid] = 0.f;      // prev buffer at t=0 (dy=0 makes update a no-op)
        zsh[tid]  = d_Z[seqbase + tid];
        zpsh[tid] = d_ZPSI[seqbase + tid];
        Psh[tid]  = d_P[seqbase + tid];
        if (tid == 0) sxs[0] = d_SX[tb];
    }
    const float S2v  = d_S2[k];
    const float SBSv = d_SBS[k];

    // ---- W and G rows in registers (32 f32x2 each) ----
    ull W2[32], Gr[32];
    {
        const float* wsrc = W0 + (size_t)k * kHD * kHD;
        #pragma unroll
        for (int p = 0; p < 32; p++) {
            int r0 = half * 64 + 2 * p;
            W2[p] = pack2(wsrc[(size_t)r0 * kHD + j], wsrc[(size_t)(r0 + 1) * kHD + j]);
        }
        const ulonglong2* grow = (const ulonglong2*)(Gsrc + (size_t)(k * kHD + j) * kHD + half * 64);
        #pragma unroll
        for (int p = 0; p < 16; p++) {
            ulonglong2 v = grow[p];
            Gr[2 * p] = v.x; Gr[2 * p + 1] = v.y;
        }
    }
    __syncthreads();

    const float cc = (float)kNH / (float)kD;
    int prevb = 2, curb = 0, nextb = 1;

    for (int t = 0; t < kT; ++t) {
        const int cur2 = t & 1;
        const int nb2 = cur2 ^ 1;

        // ======== Stage A: W -= z_{t-1} dy^T, y = z_t@W, p = zpsi_t@W ========
        const float dyO = dysh[j];
        const ull dyn2 = pack2(-dyO, -dyO);

        // prefetch next token (hidden behind the matvec)
        float nz = 0.f, nP = 0.f, nzp = 0.f, nsx = 0.f;
        if (t + 1 < kT) {
            int pb = seqbase + (t + 1) * kHD;
            if (tid < 128) {
                nz = d_Z[pb + tid];
                nP = d_P[pb + tid];
                if (tid == 0) nsx = d_SX[tb + t + 1];
            } else {
                nzp = d_ZPSI[pb + (tid - 128)];
            }
        }

        {
            const ulonglong2* zo2 = (const ulonglong2*)(zsh + prevb * 128 + half * 64);
            const ulonglong2* zc2 = (const ulonglong2*)(zsh + curb * 128 + half * 64);
            const ulonglong2* zp2 = (const ulonglong2*)(zpsh + cur2 * 128 + half * 64);
            ull ya0 = 0ULL, ya1 = 0ULL, pa0 = 0ULL, pa1 = 0ULL;
            #pragma unroll
            for (int p = 0; p < 16; p++) {
                ulonglong2 a = zo2[p], zc = zc2[p], zp = zp2[p];
                ull w0 = fma2(a.x, dyn2, W2[2 * p]);
                ull w1 = fma2(a.y, dyn2, W2[2 * p + 1]);
                W2[2 * p] = w0; W2[2 * p + 1] = w1;
                ya0 = fma2(zc.x, w0, ya0); ya1 = fma2(zc.y, w1, ya1);
                pa0 = fma2(zp.x, w0, pa0); pa1 = fma2(zp.y, w1, pa1);
            }
            float ypart = hsum2(ya0) + hsum2(ya1);
            float ppart = hsum2(pa0) + hsum2(pa1);
            ypart += __shfl_xor_sync(0xFFFFFFFFu, ypart, 1);
            ppart += __shfl_xor_sync(0xFFFFFFFFu, ppart, 1);
            if (half == 0) { ysh[j] = ypart; ppsh[j] = ppart; }

            // stash prefetched token (distinct buffers — no race with readers)
            if (t + 1 < kT) {
                if (tid < 128) {
                    zsh[nextb * 128 + tid] = nz;
                    Psh[nb2 * 128 + tid] = nP;
                    if (tid == 0) sxs[nb2] = nsx;
                } else {
                    zpsh[nb2 * 128 + (tid - 128)] = nzp;
                }
            }
            __syncthreads();   // S1

            // ======== Stage B: Gy (G in regs, y broadcast), su2/q2 + dots ========
            const ulonglong2* y2 = (const ulonglong2*)(ysh + half * 64);
            ull ga0 = 0ULL, ga1 = 0ULL;
            #pragma unroll
            for (int p = 0; p < 16; p++) {
                ulonglong2 yv = y2[p];
                ga0 = fma2(Gr[2 * p], yv.x, ga0);
                ga1 = fma2(Gr[2 * p + 1], yv.y, ga1);
            }
            float gpart = hsum2(ga0) + hsum2(ga1);
            gpart += __shfl_xor_sync(0xFFFFFFFFu, gpart, 1);
            float g2part = gpart;
            if (!fast) {
                const ulonglong2* g2r = (const ulonglong2*)(G2sh + j * PITCH + half * 64);
                ull h0 = 0ULL, h1 = 0ULL;
                #pragma unroll
                for (int p = 0; p < 16; p++) {
                    ulonglong2 gv = g2r[p];
                    ulonglong2 yv = y2[p];
                    h0 = fma2(gv.x, yv.x, h0);
                    h1 = fma2(gv.y, yv.y, h1);
                }
                g2part = hsum2(h0) + hsum2(h1);
                g2part += __shfl_xor_sync(0xFFFFFFFFu, g2part, 1);
            }
            if (half == 0) { Gysh[j] = gpart; G2ysh[j] = g2part; }

            float su2p = (half == 0) ? gpart * ypart : 0.f;
            su2p = warpsum(su2p);
            if ((tid & 31) == 0) wsumA[tid >> 5] = su2p;
            if (!fast) {
                float q2p = (half == 0) ? g2part * ypart : 0.f;
                q2p = warpsum(q2p);
                if ((tid & 31) == 0) wsumB[tid >> 5] = q2p;
            }
        }

        if (tid < 128) {
            const int i = tid;
            float yv = ysh[i];
            float p1 = g1sh[i] * yv;
            float p2 = Psh[cur2 * 128 + i] * yv;
            float p3 = zsh[curb * 128 + i] * zpsh[cur2 * 128 + i];
            float p4 = v2sh[i] * yv;
            float p5 = vbssh[i] * yv;
            p1 = warpsum(p1); p2 = warpsum(p2); p3 = warpsum(p3);
            p4 = warpsum(p4); p5 = warpsum(p5);
            if ((tid & 31) == 0) {
                int w = tid >> 5;
                dparts[w] = p1; dparts[4 + w] = p2; dparts[8 + w] = p3;
                dparts[12 + w] = p4; dparts[16 + w] = p5;
            }
        }
        __syncthreads();   // S2

        // ======== Stage E: scalars, dy, q ========
        if (tid < 128) {
            const float g1y  = dparts[0] + dparts[1] + dparts[2] + dparts[3];
            const float Pty  = dparts[4] + dparts[5] + dparts[6] + dparts[7];
            const float zz   = dparts[8] + dparts[9] + dparts[10] + dparts[11];
            const float v2y  = dparts[12] + dparts[13] + dparts[14] + dparts[15];
            const float vbsy = dparts[16] + dparts[17] + dparts[18] + dparts[19];
            float su2 = wsumA[0] + wsumA[1] + wsumA[2] + wsumA[3]
                      + wsumA[4] + wsumA[5] + wsumA[6] + wsumA[7];
            float q2 = su2;
            if (!fast)
                q2 = wsumB[0] + wsumB[1] + wsumB[2] + wsumB[3]
                   + wsumB[4] + wsumB[5] + wsumB[6] + wsumB[7];
            const float SXt = sxs[cur2];

            const float invD = 1.f / (float)kD;
            const float mu = g1y * invD;
            const float var = su2 * invD - mu * mu;
            const float rr = rsqrtf(var + kEPS);
            const float r2 = rr * rr;
            const float mdn  = (cc * invD) * (rr * (v2y - mu * S2v) + SBSv - SXt);
            const float mdnn = (cc * invD) * (r2 * (q2 - 2.f * mu * v2y + mu * mu * S2v)
                                              + rr * (vbsy - mu * SBSv)
                                              - rr * (Pty - mu * SXt));
            const float a1 = cc * r2;
            const float a2 = -r2 * mdnn;
            const float a3 = -cc * rr;
            const float a4 = -cc * r2 * mu;
            const float a5 = cc * rr;
            const float a6 = rr * (mdnn * rr * mu - mdn);
            const int i = tid;
            float dyv = a1 * G2ysh[i] + a2 * Gysh[i] + a3 * Psh[cur2 * 128 + i]
                      + a4 * v2sh[i] + a5 * vbssh[i] + a6 * g1sh[i];
            dysh[i] = dyv;
            d_Q[seqbase + t * kHD + i] = ppsh[i] - zz * dyv;
        }
        __syncthreads();   // S3

        int tmp = prevb; prevb = curb; curb = nextb; nextb = tmp;
    }
}

// ---------------- launch ----------------
extern "C" void kernel_launch(void* const* d_in, const int* in_sizes, int n_in,
                              void* d_out, int out_size) {
    const float* X   = (const float*)d_in[0];   // batch (B,T,D)
    const float* psi = (const float*)d_in[1];   // psi_k (NH,D,HD)
    const float* phi = (const float*)d_in[2];   // phi_k (NH,D,HD)
    const float* W0  = (const float*)d_in[3];   // (NH,HD,HD)
    const float* g   = (const float*)d_in[4];   // (NH,HD,D)
    const float* h   = (const float*)d_in[5];   // (NH,HD,D) -> contiguous (768,768)
    const float* lns = (const float*)d_in[6];   // (NH,D)
    const float* lnb = (const float*)d_in[7];   // (NH,D)
    float* out = (float*)d_out;
    (void)in_sizes; (void)n_in; (void)out_size;

    // device-symbol address for d_G (needed as a kernel argument)
    float* gptr = nullptr;
    cudaGetSymbolAddress((void**)&gptr, d_G);

    cudaFuncSetAttribute(scan_kernel, cudaFuncAttributeMaxDynamicSharedMemorySize, SCAN_SMEM_BYTES);

    flag_kernel<<<1, 256>>>(lns, lnb);
    consts_kernel<<<dim3(kNH, 2), 256>>>(g, lns);
    rowstats_kernel<<<kNH, 256>>>(g, lns, lnb);
    sx_kernel<<<kBT, 192>>>(X, lns);
    gemm_proj_kernel<<<dim3(1, kBT / 128, 3 * kNH), 256>>>(X, phi, psi, g, lns);
    scan_kernel<<<dim3(kNH, kB), 256, SCAN_SMEM_BYTES>>>(W0, gptr);
    gemm_out_kernel<<<dim3(kD / 128, kBT / 128), 256>>>(h, out);
}

// round 11
// speedup vs baseline: 1.1493x; 1.1493x over previous
#include <cuda_runtime.h>
#include <cuda_bf16.h>

// ---------------- problem constants ----------------
constexpr int kNH = 6;
constexpr int kD  = 768;
constexpr int kHD = 128;
constexpr int kB  = 2;
constexpr int kT  = 2048;
constexpr int kBT = kB * kT;          // 4096
constexpr int kC  = 128;              // chunk size for Q reconstruction
constexpr int kNC = kT / kC;          // 16 chunks per sequence
constexpr float kEPS = 1e-6f;

constexpr int PITCH = 132;
constexpr int GP    = 132;

typedef unsigned long long ull;

// ---------------- device scratch ----------------
__device__ float d_Z    [kNH * kBT * kHD];
__device__ float d_ZPSI [kNH * kBT * kHD];
__device__ float d_P    [kNH * kBT * kHD];
__device__ float d_DY   [kNH * kBT * kHD];
__device__ float d_Q    [kNH * kBT * kHD];
__device__ float d_CP   [kNH * kB * kNC * kHD * kHD];
__device__ float d_Wc   [kNH * kB * kNC * kHD * kHD];
__device__ float d_SX   [kNH * kBT];
__device__ float d_G    [kNH * kHD * kHD];
__device__ float d_G2   [kNH * kHD * kHD];
__device__ float d_g1   [kNH * kHD];
__device__ float d_v2   [kNH * kHD];
__device__ float d_vbs  [kNH * kHD];
__device__ float d_S2   [kNH];
__device__ float d_SBS  [kNH];
__device__ int   d_flagH[kNH];        // per-head fast-path flag (written fresh each run)

// ---------------- f32x2 helpers ----------------
__device__ __forceinline__ ull fma2(ull a, ull b, ull c) {
    ull d;
    asm("fma.rn.f32x2 %0, %1, %2, %3;" : "=l"(d) : "l"(a), "l"(b), "l"(c));
    return d;
}
__device__ __forceinline__ ull pack2(float lo, float hi) {
    ull r;
    asm("mov.b64 %0, {%1, %2};" : "=l"(r) : "f"(lo), "f"(hi));
    return r;
}
__device__ __forceinline__ float hsum2(ull v) {
    float lo, hi;
    asm("mov.b64 {%0, %1}, %2;" : "=f"(lo), "=f"(hi) : "l"(v));
    return lo + hi;
}
__device__ __forceinline__ float warpsum(float v) {
    #pragma unroll
    for (int o = 16; o > 0; o >>= 1) v += __shfl_xor_sync(0xFFFFFFFFu, v, o);
    return v;
}

// ---------------- prep: G/G2 slices (y<8), rowstats+flag (y==8) ----------------
__global__ void __launch_bounds__(256) prep_kernel(const float* __restrict__ g,
                                                   const float* __restrict__ s,
                                                   const float* __restrict__ b) {
    const int k = blockIdx.x;
    const int y = blockIdx.y;
    const int tid = threadIdx.x;

    if (y < 8) {
        __shared__ float gsh[128 * 33];
        __shared__ float wsh[32];
        const int mode = y >> 2;           // 0 -> G, 1 -> G2
        const int rb = (y & 3) * 32;       // output row base
        const int tx = tid & 15, ty = tid >> 4;
        float acc[2][8];
        #pragma unroll
        for (int r = 0; r < 2; r++)
            #pragma unroll
            for (int c = 0; c < 8; c++) acc[r][c] = 0.f;

        for (int d0 = 0; d0 < kD; d0 += 32) {
            for (int f = tid; f < 128 * 32; f += 256) {
                int i = f >> 5, dd = f & 31;
                gsh[i * 33 + dd] = g[(size_t)(k * kHD + i) * kD + d0 + dd];
            }
            if (tid < 32) {
                float sv = s[k * kD + d0 + tid];
                wsh[tid] = mode ? sv * sv : 1.0f;
            }
            __syncthreads();
            #pragma unroll 4
            for (int dd = 0; dd < 32; dd++) {
                float wv = wsh[dd];
                float a0 = gsh[(rb + ty * 2 + 0) * 33 + dd] * wv;
                float a1 = gsh[(rb + ty * 2 + 1) * 33 + dd] * wv;
                float bb[8];
                #pragma unroll
                for (int c = 0; c < 8; c++) bb[c] = gsh[(tx * 8 + c) * 33 + dd];
                #pragma unroll
                for (int c = 0; c < 8; c++) {
                    acc[0][c] = fmaf(a0, bb[c], acc[0][c]);
                    acc[1][c] = fmaf(a1, bb[c], acc[1][c]);
                }
            }
            __syncthreads();
        }
        float* dst = (mode ? d_G2 : d_G) + k * kHD * kHD;
        #pragma unroll
        for (int r = 0; r < 2; r++)
            #pragma unroll
            for (int c = 0; c < 8; c++)
                dst[(rb + ty * 2 + r) * kHD + tx * 8 + c] = acc[r][c];
    } else {
        // rowstats + per-head flag
        if (tid < 128) {
            float a1 = 0.f, a2 = 0.f, a3 = 0.f;
            const float* grow = g + (size_t)(k * kHD + tid) * kD;
            const float* srow = s + k * kD;
            const float* brow = b + k * kD;
            for (int d = 0; d < kD; d++) {
                float gv = grow[d], sv = srow[d], bv = brow[d];
                a1 += gv;
                a2 = fmaf(gv, sv * sv, a2);
                a3 = fmaf(gv, bv * sv, a3);
            }
            d_g1[k * kHD + tid]  = a1;
            d_v2[k * kHD + tid]  = a2;
            d_vbs[k * kHD + tid] = a3;
        }
        float s2p = 0.f, sbp = 0.f;
        int ok = 1;
        for (int d = tid; d < kD; d += 256) {
            float sv = s[k * kD + d], bv = b[k * kD + d];
            s2p = fmaf(sv, sv, s2p);
            sbp = fmaf(bv, sv, sbp);
            ok &= (sv == 1.0f) && (bv == 0.0f);
        }
        __shared__ float red[512];
        __shared__ int oksh;
        if (tid == 0) oksh = 1;
        red[tid] = s2p; red[256 + tid] = sbp;
        __syncthreads();
        if (!__all_sync(0xFFFFFFFFu, ok) && (tid & 31) == 0) atomicAnd(&oksh, 0);
        for (int o = 128; o > 0; o >>= 1) {
            if (tid < o) { red[tid] += red[tid + o]; red[256 + tid] += red[256 + tid + o]; }
            __syncthreads();
        }
        if (tid == 0) { d_S2[k] = red[0]; d_SBS[k] = red[256]; d_flagH[k] = oksh; }
    }
}

// ---------------- SX[k][bt] = sum_d X[bt][d]*s[k][d] ----------------
__global__ void sx_kernel(const float* __restrict__ X, const float* __restrict__ s) {
    const int bt = blockIdx.x;
    const int w = threadIdx.x >> 5;
    const int lane = threadIdx.x & 31;
    float acc = 0.f;
    for (int d0 = lane * 4; d0 < kD; d0 += 128) {
        float4 xv = *(const float4*)&X[bt * kD + d0];
        float4 sv = *(const float4*)&s[w * kD + d0];
        acc = fmaf(xv.x, sv.x, acc);
        acc = fmaf(xv.y, sv.y, acc);
        acc = fmaf(xv.z, sv.z, acc);
        acc = fmaf(xv.w, sv.w, acc);
    }
    acc = warpsum(acc);
    if (lane == 0) d_SX[w * kBT + bt] = acc;
}

// ---------------- projection GEMMs ----------------
__global__ void __launch_bounds__(256) gemm_proj_kernel(const float* __restrict__ X,
                                                        const float* __restrict__ phi,
                                                        const float* __restrict__ psi,
                                                        const float* __restrict__ g,
                                                        const float* __restrict__ s) {
    const int which = blockIdx.z % 3;
    const int head  = blockIdx.z / 3;
    const int m0 = blockIdx.y * 128;
    __shared__ float As[16 * GP];
    __shared__ float Bs[16 * GP];
    const int tid = threadIdx.x;
    const int tx = tid & 15, ty = tid >> 4;
    ull acc2[8][4];
    #pragma unroll
    for (int r = 0; r < 8; r++)
        #pragma unroll
        for (int c = 0; c < 4; c++) acc2[r][c] = 0ULL;

    const float* Bsrc = (which == 0) ? phi : psi;

    for (int k0 = 0; k0 < kD; k0 += 16) {
        {
            int m = tid >> 2, kq = tid & 3;
            #pragma unroll
            for (int h2 = 0; h2 < 2; h2++) {
                int mm = m + h2 * 64;
                float4 v = *(const float4*)&X[(size_t)(m0 + mm) * kD + k0 + kq * 4];
                As[(kq * 4 + 0) * GP + mm] = v.x;
                As[(kq * 4 + 1) * GP + mm] = v.y;
                As[(kq * 4 + 2) * GP + mm] = v.z;
                As[(kq * 4 + 3) * GP + mm] = v.w;
            }
        }
        if (which < 2) {
            int f = tid;
            #pragma unroll
            for (int it = 0; it < 2; it++, f += 256) {
                int kk = f >> 5, n4 = f & 31;
                float4 v = *(const float4*)&Bsrc[(size_t)(head * kD + k0 + kk) * kHD + n4 * 4];
                *(float4*)&Bs[kk * GP + n4 * 4] = v;
            }
        } else {
            int f = tid;
            #pragma unroll
            for (int it = 0; it < 2; it++, f += 256) {
                int jj = f >> 2, kq = f & 3;
                float4 gv = *(const float4*)&g[(size_t)(head * kHD + jj) * kD + k0 + kq * 4];
                float4 sv = *(const float4*)&s[head * kD + k0 + kq * 4];
                Bs[(kq * 4 + 0) * GP + jj] = gv.x * sv.x;
                Bs[(kq * 4 + 1) * GP + jj] = gv.y * sv.y;
                Bs[(kq * 4 + 2) * GP + jj] = gv.z * sv.z;
                Bs[(kq * 4 + 3) * GP + jj] = gv.w * sv.w;
            }
        }
        __syncthreads();
        #pragma unroll
        for (int kk = 0; kk < 16; kk++) {
            float a[8];
            *(float4*)&a[0]  = *(const float4*)&As[kk * GP + ty * 8];
            *(float4*)&a[4]  = *(const float4*)&As[kk * GP + ty * 8 + 4];
            ulonglong2 b0 = *(const ulonglong2*)&Bs[kk * GP + tx * 8];
            ulonglong2 b1 = *(const ulonglong2*)&Bs[kk * GP + tx * 8 + 4];
            #pragma unroll
            for (int r = 0; r < 8; r++) {
                ull a2 = pack2(a[r], a[r]);
                acc2[r][0] = fma2(a2, b0.x, acc2[r][0]);
                acc2[r][1] = fma2(a2, b0.y, acc2[r][1]);
                acc2[r][2] = fma2(a2, b1.x, acc2[r][2]);
                acc2[r][3] = fma2(a2, b1.y, acc2[r][3]);
            }
        }
        __syncthreads();
    }
    float* Cdst = ((which == 0) ? d_Z : (which == 1) ? d_ZPSI : d_P) + (size_t)head * kBT * kHD;
    #pragma unroll
    for (int r = 0; r < 8; r++) {
        int m = m0 + ty * 8 + r;
        *(ulonglong2*)&Cdst[(size_t)m * kHD + tx * 8]     = make_ulonglong2(acc2[r][0], acc2[r][1]);
        *(ulonglong2*)&Cdst[(size_t)m * kHD + tx * 8 + 4] = make_ulonglong2(acc2[r][2], acc2[r][3]);
    }
}

// ---------------- scan: one CTA per (head,batch); emits DY only ----------------
constexpr int SCAN_SMEM_FLOATS =
    128 * PITCH + 3 * 128 + 2 * 128 + 7 * 128 + 16 + 8 + 8 + 4;
constexpr int SCAN_SMEM_BYTES = SCAN_SMEM_FLOATS * 4;

__global__ void __launch_bounds__(256, 1) scan_kernel(const float* __restrict__ W0,
                                                      const float* __restrict__ Gsrc) {
    extern __shared__ float sm[];
    float* G2sh   = sm;
    float* zsh    = G2sh + 128 * PITCH;   // 3 x 128
    float* Psh    = zsh + 384;            // 2 x 128
    float* ysh    = Psh + 256;
    float* Gysh   = ysh + 128;
    float* G2ysh  = Gysh + 128;
    float* dysh   = G2ysh + 128;
    float* g1sh   = dysh + 128;
    float* v2sh   = g1sh + 128;
    float* vbssh  = v2sh + 128;
    float* dparts = vbssh + 128;   // 4 dots x 4 warp partials
    float* wsumA  = dparts + 16;   // su2 partials (8 warps)
    float* wsumB  = wsumA + 8;     // q2 partials
    float* sxs    = wsumB + 8;

    const int k = blockIdx.x;
    const int b = blockIdx.y;
    const int tid = threadIdx.x;
    const int j = tid >> 1;
    const int half = tid & 1;
    const bool fast = (d_flagH[0] & d_flagH[1] & d_flagH[2] &
                       d_flagH[3] & d_flagH[4] & d_flagH[5]) != 0;

    if (!fast) {
        for (int idx = tid; idx < kHD * kHD; idx += 256)
            G2sh[(idx >> 7) * PITCH + (idx & 127)] = d_G2[k * kHD * kHD + idx];
    }
    const int tb = k * kBT + b * kT;
    const int seqbase = tb * kHD;
    if (tid < 128) {
        g1sh[tid]  = d_g1[k * kHD + tid];
        v2sh[tid]  = d_v2[k * kHD + tid];
        vbssh[tid] = d_vbs[k * kHD + tid];
        dysh[tid]  = 0.f;
        zsh[2 * 128 + tid] = 0.f;
        zsh[tid]  = d_Z[seqbase + tid];
        Psh[tid]  = d_P[seqbase + tid];
        if (tid == 0) sxs[0] = d_SX[tb];
    }
    const float S2v  = d_S2[k];
    const float SBSv = d_SBS[k];

    ull W2[32], Gr[32];
    {
        const float* wsrc = W0 + (size_t)k * kHD * kHD;
        #pragma unroll
        for (int p = 0; p < 32; p++) {
            int r0 = half * 64 + 2 * p;
            W2[p] = pack2(wsrc[(size_t)r0 * kHD + j], wsrc[(size_t)(r0 + 1) * kHD + j]);
        }
        const ulonglong2* grow = (const ulonglong2*)(Gsrc + (size_t)(k * kHD + j) * kHD + half * 64);
        #pragma unroll
        for (int p = 0; p < 16; p++) {
            ulonglong2 v = grow[p];
            Gr[2 * p] = v.x; Gr[2 * p + 1] = v.y;
        }
    }
    __syncthreads();

    const float cc = (float)kNH / (float)kD;
    const float invD = 1.f / (float)kD;
    int prevb = 2, curb = 0, nextb = 1;

    for (int t = 0; t < kT; ++t) {
        const int cur2 = t & 1;
        const int nb2 = cur2 ^ 1;
        const float dyO = dysh[j];
        const ull dyn2 = pack2(-dyO, -dyO);

        float nz = 0.f, nP = 0.f, nsx = 0.f;
        if (t + 1 < kT) {
            int pb = seqbase + (t + 1) * kHD;
            if (tid < 128) {
                nz = d_Z[pb + tid];
                nP = d_P[pb + tid];
                if (tid == 0) nsx = d_SX[tb + t + 1];
            }
        }

        // Stage A: W -= z_{t-1} dy^T ; y = z_t @ W
        {
            const ulonglong2* zo2 = (const ulonglong2*)(zsh + prevb * 128 + half * 64);
            const ulonglong2* zc2 = (const ulonglong2*)(zsh + curb * 128 + half * 64);
            ull ya0 = 0ULL, ya1 = 0ULL;
            #pragma unroll
            for (int p = 0; p < 16; p++) {
                ulonglong2 a = zo2[p], zc = zc2[p];
                ull w0 = fma2(a.x, dyn2, W2[2 * p]);
                ull w1 = fma2(a.y, dyn2, W2[2 * p + 1]);
                W2[2 * p] = w0; W2[2 * p + 1] = w1;
                ya0 = fma2(zc.x, w0, ya0);
                ya1 = fma2(zc.y, w1, ya1);
            }
            float ypart = hsum2(ya0) + hsum2(ya1);
            ypart += __shfl_xor_sync(0xFFFFFFFFu, ypart, 1);
            if (half == 0) ysh[j] = ypart;

            if (t + 1 < kT && tid < 128) {
                zsh[nextb * 128 + tid] = nz;
                Psh[nb2 * 128 + tid] = nP;
                if (tid == 0) sxs[nb2] = nsx;
            }
            __syncthreads();   // S1

            // Stage B: Gy (+G2y) ; su2/q2 partials
            const ulonglong2* y2 = (const ulonglong2*)(ysh + half * 64);
            ull ga0 = 0ULL, ga1 = 0ULL;
            #pragma unroll
            for (int p = 0; p < 16; p++) {
                ulonglong2 yv = y2[p];
                ga0 = fma2(Gr[2 * p], yv.x, ga0);
                ga1 = fma2(Gr[2 * p + 1], yv.y, ga1);
            }
            float gpart = hsum2(ga0) + hsum2(ga1);
            gpart += __shfl_xor_sync(0xFFFFFFFFu, gpart, 1);
            float g2part = gpart;
            if (!fast) {
                const ulonglong2* g2r = (const ulonglong2*)(G2sh + j * PITCH + half * 64);
                ull h0 = 0ULL, h1 = 0ULL;
                #pragma unroll
                for (int p = 0; p < 16; p++) {
                    ulonglong2 gv = g2r[p];
                    ulonglong2 yv = y2[p];
                    h0 = fma2(gv.x, yv.x, h0);
                    h1 = fma2(gv.y, yv.y, h1);
                }
                g2part = hsum2(h0) + hsum2(h1);
                g2part += __shfl_xor_sync(0xFFFFFFFFu, g2part, 1);
            }
            if (half == 0) { Gysh[j] = gpart; G2ysh[j] = g2part; }

            float yb = __shfl_xor_sync(0xFFFFFFFFu, (half == 0) ? 0.f : 0.f, 0);  // no-op keep regs tight
            float su2p = (half == 0) ? gpart * ysh[j] : 0.f;
            su2p = warpsum(su2p);
            if ((tid & 31) == 0) wsumA[tid >> 5] = su2p;
            if (!fast) {
                float q2p = (half == 0) ? g2part * ysh[j] : 0.f;
                q2p = warpsum(q2p);
                if ((tid & 31) == 0) wsumB[tid >> 5] = q2p;
            }
            (void)yb;
        }

        if (tid < 128) {
            const int i = tid;
            float yv = ysh[i];
            float p1 = g1sh[i] * yv;
            float p2 = Psh[cur2 * 128 + i] * yv;
            float p3 = v2sh[i] * yv;
            float p4 = vbssh[i] * yv;
            p1 = warpsum(p1); p2 = warpsum(p2); p3 = warpsum(p3); p4 = warpsum(p4);
            if ((tid & 31) == 0) {
                int w = tid >> 5;
                dparts[w] = p1; dparts[4 + w] = p2;
                dparts[8 + w] = p3; dparts[12 + w] = p4;
            }
        }
        __syncthreads();   // S2

        // Stage E: scalars, dy
        if (tid < 128) {
            const float g1y  = dparts[0] + dparts[1] + dparts[2] + dparts[3];
            const float Pty  = dparts[4] + dparts[5] + dparts[6] + dparts[7];
            const float v2y  = dparts[8] + dparts[9] + dparts[10] + dparts[11];
            const float vbsy = dparts[12] + dparts[13] + dparts[14] + dparts[15];
            float su2 = wsumA[0] + wsumA[1] + wsumA[2] + wsumA[3]
                      + wsumA[4] + wsumA[5] + wsumA[6] + wsumA[7];
            float q2 = su2;
            if (!fast)
                q2 = wsumB[0] + wsumB[1] + wsumB[2] + wsumB[3]
                   + wsumB[4] + wsumB[5] + wsumB[6] + wsumB[7];
            const float SXt = sxs[cur2];

            const float mu = g1y * invD;
            const float var = su2 * invD - mu * mu;
            const float rr = rsqrtf(var + kEPS);
            const float r2 = rr * rr;
            const float mdn  = (cc * invD) * (rr * (v2y - mu * S2v) + SBSv - SXt);
            const float mdnn = (cc * invD) * (r2 * (q2 - 2.f * mu * v2y + mu * mu * S2v)
                                              + rr * (vbsy - mu * SBSv)
                                              - rr * (Pty - mu * SXt));
            const float a1 = cc * r2;
            const float a2 = -r2 * mdnn;
            const float a3 = -cc * rr;
            const float a4 = -cc * r2 * mu;
            const float a5 = cc * rr;
            const float a6 = rr * (mdnn * rr * mu - mdn);
            const int i = tid;
            float gy = Gysh[i];
            float g2y = fast ? gy : G2ysh[i];
            float dyv = a1 * g2y + a2 * gy + a3 * Psh[cur2 * 128 + i]
                      + a4 * v2sh[i] + a5 * vbssh[i] + a6 * g1sh[i];
            dysh[i] = dyv;
            d_DY[seqbase + t * kHD + i] = dyv;
        }
        __syncthreads();   // S3

        int tmp = prevb; prevb = curb; curb = nextb; nextb = tmp;
    }
}

// ---------------- CP_c = Z_c^T @ DY_c ; grid (kNC, 12) ----------------
__global__ void __launch_bounds__(256) chunkA_kernel() {
    const int c = blockIdx.x;
    const int kb = blockIdx.y;
    const int base = (kb >> 1) * kBT + (kb & 1) * kT + c * kC;
    __shared__ float As[16 * GP];
    __shared__ float Bs[16 * GP];
    const int tid = threadIdx.x;
    const int tx = tid & 15, ty = tid >> 4;
    float acc[8][8];
    #pragma unroll
    for (int r = 0; r < 8; r++)
        #pragma unroll
        for (int q = 0; q < 8; q++) acc[r][q] = 0.f;

    for (int r0 = 0; r0 < kC; r0 += 16) {
        int f = tid;
        #pragma unroll
        for (int it = 0; it < 2; it++, f += 256) {
            int kk = f >> 5, c4 = f & 31;
            *(float4*)&As[kk * GP + c4 * 4] =
                *(const float4*)&d_Z[(size_t)(base + r0 + kk) * kHD + c4 * 4];
            *(float4*)&Bs[kk * GP + c4 * 4] =
                *(const float4*)&d_DY[(size_t)(base + r0 + kk) * kHD + c4 * 4];
        }
        __syncthreads();
        #pragma unroll
        for (int kk = 0; kk < 16; kk++) {
            float a[8], bb[8];
            *(float4*)&a[0]  = *(const float4*)&As[kk * GP + ty * 8];
            *(float4*)&a[4]  = *(const float4*)&As[kk * GP + ty * 8 + 4];
            *(float4*)&bb[0] = *(const float4*)&Bs[kk * GP + tx * 8];
            *(float4*)&bb[4] = *(const float4*)&Bs[kk * GP + tx * 8 + 4];
            #pragma unroll
            for (int r = 0; r < 8; r++)
                #pragma unroll
                for (int q = 0; q < 8; q++) acc[r][q] = fmaf(a[r], bb[q], acc[r][q]);
        }
        __syncthreads();
    }
    float* dst = d_CP + (size_t)(kb * kNC + c) * kHD * kHD;
    #pragma unroll
    for (int r = 0; r < 8; r++) {
        int i = ty * 8 + r;
        *(float4*)&dst[(size_t)i * kHD + tx * 8]     = make_float4(acc[r][0], acc[r][1], acc[r][2], acc[r][3]);
        *(float4*)&dst[(size_t)i * kHD + tx * 8 + 4] = make_float4(acc[r][4], acc[r][5], acc[r][6], acc[r][7]);
    }
}

// ---------------- W_c prefix ; grid (12) ----------------
__global__ void __launch_bounds__(256) prefix_kernel(const float* __restrict__ W0) {
    const int kb = blockIdx.x;
    const int k = kb >> 1;
    const int tid = threadIdx.x;
    float w[64];
    #pragma unroll
    for (int e = 0; e < 64; e++) w[e] = W0[(size_t)k * kHD * kHD + e * 256 + tid];
    for (int c = 0; c < kNC; c++) {
        float* dst = d_Wc + (size_t)(kb * kNC + c) * kHD * kHD;
        #pragma unroll
        for (int e = 0; e < 64; e++) dst[e * 256 + tid] = w[e];
        if (c < kNC - 1) {
            const float* cp = d_CP + (size_t)(kb * kNC + c) * kHD * kHD;
            #pragma unroll
            for (int e = 0; e < 64; e++) w[e] -= cp[e * 256 + tid];
        }
    }
}

// ---------------- Q_c = Zpsi_c@W_c - tril(Zpsi_c Z_c^T)@DY_c ; grid (kNC, 12) ----------------
constexpr int QR_SMEM_FLOATS = 128 * PITCH + 2 * 16 * GP;
constexpr int QR_SMEM_BYTES = QR_SMEM_FLOATS * 4;

__global__ void __launch_bounds__(256) qrecon_kernel() {
    const int c = blockIdx.x;
    const int kb = blockIdx.y;
    const int base = (kb >> 1) * kBT + (kb & 1) * kT + c * kC;
    extern __shared__ float qs[];
    float* Msh = qs;                 // tril(S) stored transposed: Msh[r*PITCH + t]
    float* As  = Msh + 128 * PITCH;
    float* Bs  = As + 16 * GP;
    const int tid = threadIdx.x;
    const int tx = tid & 15, ty = tid >> 4;
    const int m = tid >> 2, kq = tid & 3;

    float acc[8][8];
    #pragma unroll
    for (int r = 0; r < 8; r++)
        #pragma unroll
        for (int q = 0; q < 8; q++) acc[r][q] = 0.f;

    // ---- Phase 1: S = Zpsi_c @ Z_c^T (contraction over d) ----
    for (int d0 = 0; d0 < kHD; d0 += 16) {
        #pragma unroll
        for (int h2 = 0; h2 < 2; h2++) {
            int mm = m + h2 * 64;
            float4 va = *(const float4*)&d_ZPSI[(size_t)(base + mm) * kHD + d0 + kq * 4];
            As[(kq * 4 + 0) * GP + mm] = va.x;
            As[(kq * 4 + 1) * GP + mm] = va.y;
            As[(kq * 4 + 2) * GP + mm] = va.z;
            As[(kq * 4 + 3) * GP + mm] = va.w;
            float4 vb = *(const float4*)&d_Z[(size_t)(base + mm) * kHD + d0 + kq * 4];
            Bs[(kq * 4 + 0) * GP + mm] = vb.x;
            Bs[(kq * 4 + 1) * GP + mm] = vb.y;
            Bs[(kq * 4 + 2) * GP + mm] = vb.z;
            Bs[(kq * 4 + 3) * GP + mm] = vb.w;
        }
        __syncthreads();
        #pragma unroll
        for (int kk = 0; kk < 16; kk++) {
            float a[8], bb[8];
            *(float4*)&a[0]  = *(const float4*)&As[kk * GP + ty * 8];
            *(float4*)&a[4]  = *(const float4*)&As[kk * GP + ty * 8 + 4];
            *(float4*)&bb[0] = *(const float4*)&Bs[kk * GP + tx * 8];
            *(float4*)&bb[4] = *(const float4*)&Bs[kk * GP + tx * 8 + 4];
            #pragma unroll
            for (int r = 0; r < 8; r++)
                #pragma unroll
                for (int q = 0; q < 8; q++) acc[r][q] = fmaf(a[r], bb[q], acc[r][q]);
        }
        __syncthreads();
    }
    // masked transposed store: Msh[r][t] = (r <= t) ? S[t][r] : 0
    #pragma unroll
    for (int r = 0; r < 8; r++) {
        int t = ty * 8 + r;
        #pragma unroll
        for (int q = 0; q < 8; q++) {
            int rr = tx * 8 + q;
            Msh[rr * PITCH + t] = (rr <= t) ? acc[r][q] : 0.f;
        }
    }
    #pragma unroll
    for (int r = 0; r < 8; r++)
        #pragma unroll
        for (int q = 0; q < 8; q++) acc[r][q] = 0.f;
    __syncthreads();

    // ---- Phase 2: acc = Zpsi_c @ W_c (contraction over d) ----
    const float* Wc = d_Wc + (size_t)(kb * kNC + c) * kHD * kHD;
    for (int d0 = 0; d0 < kHD; d0 += 16) {
        #pragma unroll
        for (int h2 = 0; h2 < 2; h2++) {
            int mm = m + h2 * 64;
            float4 va = *(const float4*)&d_ZPSI[(size_t)(base + mm) * kHD + d0 + kq * 4];
            As[(kq * 4 + 0) * GP + mm] = va.x;
            As[(kq * 4 + 1) * GP + mm] = va.y;
            As[(kq * 4 + 2) * GP + mm] = va.z;
            As[(kq * 4 + 3) * GP + mm] = va.w;
        }
        {
            int f = tid;
            #pragma unroll
            for (int it = 0; it < 2; it++, f += 256) {
                int kk = f >> 5, c4 = f & 31;
                *(float4*)&Bs[kk * GP + c4 * 4] =
                    *(const float4*)&Wc[(size_t)(d0 + kk) * kHD + c4 * 4];
            }
        }
        __syncthreads();
        #pragma unroll
        for (int kk = 0; kk < 16; kk++) {
            float a[8], bb[8];
            *(float4*)&a[0]  = *(const float4*)&As[kk * GP + ty * 8];
            *(float4*)&a[4]  = *(const float4*)&As[kk * GP + ty * 8 + 4];
            *(float4*)&bb[0] = *(const float4*)&Bs[kk * GP + tx * 8];
            *(float4*)&bb[4] = *(const float4*)&Bs[kk * GP + tx * 8 + 4];
            #pragma unroll
            for (int r = 0; r < 8; r++)
                #pragma unroll
                for (int q = 0; q < 8; q++) acc[r][q] = fmaf(a[r], bb[q], acc[r][q]);
        }
        __syncthreads();
    }

    // ---- Phase 3: acc -= tril(S) @ DY_c (contraction over r) ----
    for (int r0 = 0; r0 < kC; r0 += 16) {
        int f = tid;
        #pragma unroll
        for (int it = 0; it < 2; it++, f += 256) {
            int kk = f >> 5, c4 = f & 31;
            *(float4*)&Bs[kk * GP + c4 * 4] =
                *(const float4*)&d_DY[(size_t)(base + r0 + kk) * kHD + c4 * 4];
        }
        __syncthreads();
        #pragma unroll
        for (int kk = 0; kk < 16; kk++) {
            float a[8], bb[8];
            *(float4*)&a[0]  = *(const float4*)&Msh[(r0 + kk) * PITCH + ty * 8];
            *(float4*)&a[4]  = *(const float4*)&Msh[(r0 + kk) * PITCH + ty * 8 + 4];
            *(float4*)&bb[0] = *(const float4*)&Bs[kk * GP + tx * 8];
            *(float4*)&bb[4] = *(const float4*)&Bs[kk * GP + tx * 8 + 4];
            #pragma unroll
            for (int r = 0; r < 8; r++)
                #pragma unroll
                for (int q = 0; q < 8; q++) acc[r][q] = fmaf(-a[r], bb[q], acc[r][q]);
        }
        __syncthreads();
    }

    #pragma unroll
    for (int r = 0; r < 8; r++) {
        int t = base + ty * 8 + r;
        *(float4*)&d_Q[(size_t)t * kHD + tx * 8]     = make_float4(acc[r][0], acc[r][1], acc[r][2], acc[r][3]);
        *(float4*)&d_Q[(size_t)t * kHD + tx * 8 + 4] = make_float4(acc[r][4], acc[r][5], acc[r][6], acc[r][7]);
    }
}

// ---------------- output GEMM ----------------
__global__ void __launch_bounds__(256) gemm_out_kernel(const float* __restrict__ h,
                                                       float* __restrict__ out) {
    const int n0 = blockIdx.x * 128;
    const int m0 = blockIdx.y * 128;
    __shared__ float As[16 * GP];
    __shared__ float Bs[16 * GP];
    const int tid = threadIdx.x;
    const int tx = tid & 15, ty = tid >> 4;
    ull acc2[8][4];
    #pragma unroll
    for (int r = 0; r < 8; r++)
        #pragma unroll
        for (int c = 0; c < 4; c++) acc2[r][c] = 0ULL;

    for (int k0 = 0; k0 < kNH * kHD; k0 += 16) {
        const int head = k0 >> 7;
        const int j0 = k0 & 127;
        const float* Aq = d_Q + (size_t)head * kBT * kHD;
        {
            int m = tid >> 2, kq = tid & 3;
            #pragma unroll
            for (int h2 = 0; h2 < 2; h2++) {
                int mm = m + h2 * 64;
                float4 v = *(const float4*)&Aq[(size_t)(m0 + mm) * kHD + j0 + kq * 4];
                As[(kq * 4 + 0) * GP + mm] = v.x;
                As[(kq * 4 + 1) * GP + mm] = v.y;
                As[(kq * 4 + 2) * GP + mm] = v.z;
                As[(kq * 4 + 3) * GP + mm] = v.w;
            }
        }
        {
            int f = tid;
            #pragma unroll
            for (int it = 0; it < 2; it++, f += 256) {
                int kk = f >> 5, n4 = f & 31;
                float4 v = *(const float4*)&h[(size_t)(k0 + kk) * kD + n0 + n4 * 4];
                *(float4*)&Bs[kk * GP + n4 * 4] = v;
            }
        }
        __syncthreads();
        #pragma unroll
        for (int kk = 0; kk < 16; kk++) {
            float a[8];
            *(float4*)&a[0]  = *(const float4*)&As[kk * GP + ty * 8];
            *(float4*)&a[4]  = *(const float4*)&As[kk * GP + ty * 8 + 4];
            ulonglong2 b0 = *(const ulonglong2*)&Bs[kk * GP + tx * 8];
            ulonglong2 b1 = *(const ulonglong2*)&Bs[kk * GP + tx * 8 + 4];
            #pragma unroll
            for (int r = 0; r < 8; r++) {
                ull a2 = pack2(a[r], a[r]);
                acc2[r][0] = fma2(a2, b0.x, acc2[r][0]);
                acc2[r][1] = fma2(a2, b0.y, acc2[r][1]);
                acc2[r][2] = fma2(a2, b1.x, acc2[r][2]);
                acc2[r][3] = fma2(a2, b1.y, acc2[r][3]);
            }
        }
        __syncthreads();
    }
    #pragma unroll
    for (int r = 0; r < 8; r++) {
        int mm = m0 + ty * 8 + r;
        *(ulonglong2*)&out[(size_t)mm * kD + n0 + tx * 8]     = make_ulonglong2(acc2[r][0], acc2[r][1]);
        *(ulonglong2*)&out[(size_t)mm * kD + n0 + tx * 8 + 4] = make_ulonglong2(acc2[r][2], acc2[r][3]);
    }
}

// ---------------- launch ----------------
extern "C" void kernel_launch(void* const* d_in, const int* in_sizes, int n_in,
                              void* d_out, int out_size) {
    const float* X   = (const float*)d_in[0];
    const float* psi = (const float*)d_in[1];
    const float* phi = (const float*)d_in[2];
    const float* W0  = (const float*)d_in[3];
    const float* g   = (const float*)d_in[4];
    const float* h   = (const float*)d_in[5];
    const float* lns = (const float*)d_in[6];
    const float* lnb = (const float*)d_in[7];
    float* out = (float*)d_out;
    (void)in_sizes; (void)n_in; (void)out_size;

    float* gptr = nullptr;
    cudaGetSymbolAddress((void**)&gptr, d_G);

    cudaFuncSetAttribute(scan_kernel, cudaFuncAttributeMaxDynamicSharedMemorySize, SCAN_SMEM_BYTES);
    cudaFuncSetAttribute(qrecon_kernel, cudaFuncAttributeMaxDynamicSharedMemorySize, QR_SMEM_BYTES);

    prep_kernel<<<dim3(kNH, 9), 256>>>(g, lns, lnb);
    sx_kernel<<<kBT, 192>>>(X, lns);
    gemm_proj_kernel<<<dim3(1, kBT / 128, 3 * kNH), 256>>>(X, phi, psi, g, lns);
    scan_kernel<<<dim3(kNH, kB), 256, SCAN_SMEM_BYTES>>>(W0, gptr);
    chunkA_kernel<<<dim3(kNC, kNH * kB), 256>>>();
    prefix_kernel<<<kNH * kB, 256>>>(W0);
    qrecon_kernel<<<dim3(kNC, kNH * kB), 256, QR_SMEM_BYTES>>>();
    gemm_out_kernel<<<dim3(kD / 128, kBT / 128), 256>>>(h, out);
}